// round 4
// baseline (speedup 1.0000x reference)
#include <cuda_runtime.h>
#include <math.h>

#define NDIM 8
#define THREADS 256
#define BLOCKS (148 * 6)

// u4: [N, 8] fp32 viewed as 2x float4 per point
// grid: [8, ninc+1] row-major
// out layout: x [N,8] then log_jac [N]
__global__ void __launch_bounds__(THREADS)
vegas_map_kernel(const float4* __restrict__ u4,
                 const float*  __restrict__ grid,
                 float4*       __restrict__ x4,
                 float*        __restrict__ logj,
                 int n, int ninc)
{
    const int gw = ninc + 1;
    extern __shared__ float sg[];                       // NDIM * (ninc+1)
    for (int i = threadIdx.x; i < NDIM * gw; i += blockDim.x)
        sg[i] = grid[i];
    __syncthreads();

    const float fninc = (float)ninc;
    const float logC  = (float)NDIM * logf(fninc);      // sum of log(ninc) terms

    const int stride = gridDim.x * blockDim.x;
    for (int p = blockIdx.x * blockDim.x + threadIdx.x; p < n; p += stride) {
        float4 a = u4[2 * p];
        float4 b = u4[2 * p + 1];
        float uu[NDIM] = {a.x, a.y, a.z, a.w, b.x, b.y, b.z, b.w};
        float xx[NDIM];
        float prod = 1.0f;

        #pragma unroll
        for (int d = 0; d < NDIM; d++) {
            float t  = uu[d] * fninc;
            float ft = floorf(t);
            int   iu = (int)ft;
            float du = t - ft;
            bool  in = (iu < ninc);
            int   ic = in ? iu : (ninc - 1);
            if (ic < 0) ic = 0;                         // safety clamp (u >= 0 anyway)
            float glo = sg[d * gw + ic];
            float ghi = sg[d * gw + ic + 1];
            float h   = ghi - glo;                      // == inc[d][ic] bit-exactly
            xx[d] = in ? fmaf(h, du, glo) : ghi;        // ghi == grid[d][ninc] when !in
            prod *= h;                                  // fac = h * ninc; ninc folded into logC
        }

        x4[2 * p]     = make_float4(xx[0], xx[1], xx[2], xx[3]);
        x4[2 * p + 1] = make_float4(xx[4], xx[5], xx[6], xx[7]);
        logj[p] = logf(prod) + logC;
    }
}

extern "C" void kernel_launch(void* const* d_in, const int* in_sizes, int n_in,
                              void* d_out, int out_size)
{
    const float* u    = (const float*)d_in[0];   // [N, 8]
    const float* grid = (const float*)d_in[1];   // [8, ninc+1]
    // d_in[2] = inc  (unused: reconstructed from grid, bit-exact)
    // d_in[3] = ninc (derived from sizes instead; avoids device scalar read)

    const int n    = in_sizes[0] / NDIM;
    const int gw   = in_sizes[1] / NDIM;         // ninc + 1
    const int ninc = gw - 1;

    float* x    = (float*)d_out;                 // [N, 8]
    float* logj = (float*)d_out + (size_t)n * NDIM;

    const int smem = NDIM * gw * (int)sizeof(float);

    int blocks = BLOCKS;
    int per_grid = blocks * THREADS;
    if (per_grid > n) blocks = (n + THREADS - 1) / THREADS;

    vegas_map_kernel<<<blocks, THREADS, smem>>>(
        (const float4*)u, grid, (float4*)x, logj, n, ninc);
}